// round 6
// baseline (speedup 1.0000x reference)
#include <cuda_runtime.h>
#include <cuda_bf16.h>
#include <math.h>
#include <stdint.h>

// Problem constants
#define B_   4
#define S_   1024
#define T_   4096
#define H_   32
#define D_   80
#define HID_ 2560
#define QKV_N 7680
#define HALF_ 16
#define SCALE_ 0.11180339887498948f

// ---------------------------------------------------------------------------
// Scratch (device globals)
// ---------------------------------------------------------------------------
__device__ float g_qkv [(size_t)T_ * QKV_N];
__device__ float g_attn[(size_t)T_ * HID_];
__device__ float g_hidT[(size_t)T_ * HID_];
__device__ float g_wqkvT[(size_t)QKV_N * HID_];
__device__ float g_wdT [(size_t)HID_ * HID_];

// ---------------------------------------------------------------------------
// Helpers
// ---------------------------------------------------------------------------
__device__ __forceinline__ float tf32r(float x) {
    uint32_t r;
    asm("cvt.rna.tf32.f32 %0, %1;" : "=r"(r) : "f"(x));
    return __uint_as_float(r);
}

#define CP_ASYNC16(dst, src) \
    asm volatile("cp.async.cg.shared.global [%0], [%1], 16;" :: "r"(dst), "l"(src) : "memory")
#define CP_COMMIT() asm volatile("cp.async.commit_group;" ::: "memory")
#define CP_WAIT0()  asm volatile("cp.async.wait_group 0;" ::: "memory")
#define CP_WAIT1()  asm volatile("cp.async.wait_group 1;" ::: "memory")

#define MMA_TF32(d, a, b) \
    asm volatile("mma.sync.aligned.m16n8k8.row.col.f32.tf32.tf32.f32 " \
        "{%0,%1,%2,%3}, {%4,%5,%6,%7}, {%8,%9}, {%0,%1,%2,%3};" \
        : "+f"((d)[0]), "+f"((d)[1]), "+f"((d)[2]), "+f"((d)[3]) \
        : "r"((a)[0]), "r"((a)[1]), "r"((a)[2]), "r"((a)[3]), \
          "r"((b)[0]), "r"((b)[1]))

__device__ __forceinline__ uint32_t smem_u32(const void* p) {
    uint32_t a;
    asm("{ .reg .u64 t; cvta.to.shared.u64 t, %1; cvt.u32.u64 %0, t; }"
        : "=r"(a) : "l"(p));
    return a;
}

// ---------------------------------------------------------------------------
// tf32 mma.sync GEMM: C[M,N] = A[M,K] @ W[N,K]^T + bias[N]
// CTA tile 128x256, BK=16, 8 warps, warp tile 64(M)x64(N) = 4x8 m16n8k8 frags.
// Double-buffered cp.async, dynamic smem, 1 CTA/SM.
// ---------------------------------------------------------------------------
#define GM 128
#define GN 256
#define GKC 16
#define PITCH 20
#define A_STG_F (GM * PITCH)            // 2560 floats per stage
#define B_STG_F (GN * PITCH)            // 5120 floats per stage
#define GEMM_SMEM ((2 * A_STG_F + 2 * B_STG_F) * 4)   // 61440 bytes

__global__ __launch_bounds__(256, 1) void mma_gemm(
    const float* __restrict__ A, const float* __restrict__ W,
    const float* __restrict__ bias, float* __restrict__ C,
    int M, int N, int K)
{
    extern __shared__ float smf[];
    float* Asm = smf;                   // [2][A_STG_F]
    float* Bsm = smf + 2 * A_STG_F;     // [2][B_STG_F]

    const int tid  = threadIdx.x;
    const int wid  = tid >> 5;
    const int lane = tid & 31;
    const int gid  = lane >> 2;       // 0..7
    const int tig  = lane & 3;        // 0..3
    const int wm   = wid >> 2;        // 0..1 -> M offset 64*wm
    const int wn   = wid & 3;         // 0..3 -> N offset 64*wn
    const int m0 = blockIdx.y * GM;
    const int n0 = blockIdx.x * GN;
    const int nk = K / GKC;

    const uint32_t sa = smem_u32(Asm);
    const uint32_t sb = smem_u32(Bsm);

    // cp.async mapping: A 512 chunks (2/thread), B 1024 chunks (4/thread).
    const float* srcA[2]; uint32_t dA[2];
#pragma unroll
    for (int u = 0; u < 2; u++) {
        int idx = tid + u * 256;
        int row = idx >> 2, kc = idx & 3;
        srcA[u] = A + (size_t)(m0 + row) * K + kc * 4;
        dA[u] = (uint32_t)(row * PITCH + kc * 4) * 4;
    }
    const float* srcB[4]; uint32_t dB[4];
#pragma unroll
    for (int u = 0; u < 4; u++) {
        int idx = tid + u * 256;
        int row = idx >> 2, kc = idx & 3;
        srcB[u] = W + (size_t)(n0 + row) * K + kc * 4;
        dB[u] = (uint32_t)(row * PITCH + kc * 4) * 4;
    }

    float acc[4][8][4];
#pragma unroll
    for (int mt = 0; mt < 4; mt++)
#pragma unroll
        for (int nt = 0; nt < 8; nt++)
#pragma unroll
            for (int r = 0; r < 4; r++) acc[mt][nt][r] = 0.0f;

    // Prologue: stage 0
#pragma unroll
    for (int u = 0; u < 2; u++) CP_ASYNC16(sa + dA[u], srcA[u]);
#pragma unroll
    for (int u = 0; u < 4; u++) CP_ASYNC16(sb + dB[u], srcB[u]);
    CP_COMMIT();

    for (int i = 0; i < nk; i++) {
        const int s = i & 1;
        if (i + 1 < nk) {
            const int s2 = (i + 1) & 1;
            const int kt = (i + 1) * GKC;
            const uint32_t ab = sa + s2 * (A_STG_F * 4);
            const uint32_t bb = sb + s2 * (B_STG_F * 4);
#pragma unroll
            for (int u = 0; u < 2; u++) CP_ASYNC16(ab + dA[u], srcA[u] + kt);
#pragma unroll
            for (int u = 0; u < 4; u++) CP_ASYNC16(bb + dB[u], srcB[u] + kt);
            CP_COMMIT();
            CP_WAIT1();
        } else {
            CP_WAIT0();
        }
        __syncthreads();

        const float* as = Asm + s * A_STG_F;
        const float* bs = Bsm + s * B_STG_F;
#pragma unroll
        for (int ks = 0; ks < 2; ks++) {
            const int k0 = ks * 8;
            uint32_t af[4][4], bf[8][2];
#pragma unroll
            for (int mt = 0; mt < 4; mt++) {
                int r = wm * 64 + mt * 16 + gid;
                af[mt][0] = __float_as_uint(as[r * PITCH + k0 + tig]);
                af[mt][1] = __float_as_uint(as[(r + 8) * PITCH + k0 + tig]);
                af[mt][2] = __float_as_uint(as[r * PITCH + k0 + tig + 4]);
                af[mt][3] = __float_as_uint(as[(r + 8) * PITCH + k0 + tig + 4]);
            }
#pragma unroll
            for (int nt = 0; nt < 8; nt++) {
                int c = wn * 64 + nt * 8 + gid;
                bf[nt][0] = __float_as_uint(bs[c * PITCH + k0 + tig]);
                bf[nt][1] = __float_as_uint(bs[c * PITCH + k0 + tig + 4]);
            }
#pragma unroll
            for (int mt = 0; mt < 4; mt++)
#pragma unroll
                for (int nt = 0; nt < 8; nt++)
                    MMA_TF32(acc[mt][nt], af[mt], bf[nt]);
        }
        __syncthreads();
    }

    // Epilogue: bias + store (same lane mapping as before, proven).
#pragma unroll
    for (int mt = 0; mt < 4; mt++) {
        int r = m0 + wm * 64 + mt * 16 + gid;
#pragma unroll
        for (int nt = 0; nt < 8; nt++) {
            int c = n0 + wn * 64 + nt * 8 + tig * 2;
            float b0 = bias[c], b1 = bias[c + 1];
            float2 v0 = make_float2(acc[mt][nt][0] + b0, acc[mt][nt][1] + b1);
            float2 v1 = make_float2(acc[mt][nt][2] + b0, acc[mt][nt][3] + b1);
            *(float2*)(C + (size_t)r * N + c)       = v0;
            *(float2*)(C + (size_t)(r + 8) * N + c) = v1;
        }
    }
}

// ---------------------------------------------------------------------------
// tf32 round (RNA) elementwise convert
// ---------------------------------------------------------------------------
__global__ __launch_bounds__(256) void cvt_tf32_kernel(
    const float4* __restrict__ in, float4* __restrict__ out, int n4)
{
    int i = blockIdx.x * 256 + threadIdx.x;
    if (i >= n4) return;
    float4 v = in[i];
    v.x = tf32r(v.x); v.y = tf32r(v.y); v.z = tf32r(v.z); v.w = tf32r(v.w);
    out[i] = v;
}

// ---------------------------------------------------------------------------
// Partial rotary (in place on q,k of qkv)
// ---------------------------------------------------------------------------
__global__ __launch_bounds__(256) void rope_kernel(
    float* __restrict__ qkv, const float* __restrict__ cosp,
    const float* __restrict__ sinp)
{
    int idx = blockIdx.x * blockDim.x + threadIdx.x;
    int i = idx & (HALF_ - 1);
    int h = (idx >> 4) & (H_ - 1);
    int t = (idx >> 9) & (T_ - 1);
    int which = idx >> 21;
    float* base = qkv + (size_t)t * QKV_N + which * HID_ + h * D_;
    float c = cosp[t * HALF_ + i];
    float s = sinp[t * HALF_ + i];
    float x1 = base[i];
    float x2 = base[i + HALF_];
    base[i]         = x1 * c - x2 * s;
    base[i + HALF_] = x2 * c + x1 * s;
}

// ---------------------------------------------------------------------------
// Causal flash attention (fp32 SIMT), epilogue rounds to tf32 for dense GEMM.
// ---------------------------------------------------------------------------
#define BQ 64
#define BKV 64
#define PQ 84
#define ATTN_SMEM_FLOATS (BQ*PQ + BKV*PQ + BKV*D_ + BQ*BKV)
#define ATTN_SMEM_BYTES  (ATTN_SMEM_FLOATS * 4)

__global__ __launch_bounds__(256) void attn_kernel(
    const float* __restrict__ qkv, float* __restrict__ outp)
{
    extern __shared__ float sm[];
    float* Qs = sm;
    float* Ks = Qs + BQ * PQ;
    float* Vs = Ks + BKV * PQ;
    float* Ps = Vs + BKV * D_;

    const int bh = blockIdx.y;
    const int b  = bh >> 5;
    const int h  = bh & 31;
    const int qt = blockIdx.x;
    const int q0 = qt * BQ;
    const int tid = threadIdx.x;
    const int tx = tid & 15;
    const int ty = tid >> 4;

    const float* Qg = qkv + (size_t)(b * S_) * QKV_N + h * D_;
    const float* Kg = Qg + HID_;
    const float* Vg = Qg + 2 * HID_;

    for (int u = tid; u < BQ * 20; u += 256) {
        int r = u / 20, c4 = u % 20;
        *(float4*)&Qs[r * PQ + c4 * 4] =
            *(const float4*)(Qg + (size_t)(q0 + r) * QKV_N + c4 * 4);
    }

    float m_i[4], l_i[4], acc[4][5];
#pragma unroll
    for (int i = 0; i < 4; i++) {
        m_i[i] = -1e30f;
        l_i[i] = 0.0f;
#pragma unroll
        for (int cc = 0; cc < 5; cc++) acc[i][cc] = 0.0f;
    }

    for (int jt = 0; jt <= qt; jt++) {
        for (int u = tid; u < BKV * 20; u += 256) {
            int r = u / 20, c4 = u % 20;
            *(float4*)&Ks[r * PQ  + c4 * 4] =
                *(const float4*)(Kg + (size_t)(jt * BKV + r) * QKV_N + c4 * 4);
            *(float4*)&Vs[r * D_ + c4 * 4] =
                *(const float4*)(Vg + (size_t)(jt * BKV + r) * QKV_N + c4 * 4);
        }
        __syncthreads();

        float s[4][4];
#pragma unroll
        for (int i = 0; i < 4; i++)
#pragma unroll
            for (int jj = 0; jj < 4; jj++) s[i][jj] = 0.0f;

        for (int d = 0; d < D_; d += 4) {
            float4 qv[4], kv[4];
#pragma unroll
            for (int i = 0; i < 4; i++)
                qv[i] = *(const float4*)&Qs[(ty * 4 + i) * PQ + d];
#pragma unroll
            for (int jj = 0; jj < 4; jj++)
                kv[jj] = *(const float4*)&Ks[(tx + 16 * jj) * PQ + d];
#pragma unroll
            for (int i = 0; i < 4; i++)
#pragma unroll
                for (int jj = 0; jj < 4; jj++) {
                    s[i][jj] = fmaf(qv[i].x, kv[jj].x, s[i][jj]);
                    s[i][jj] = fmaf(qv[i].y, kv[jj].y, s[i][jj]);
                    s[i][jj] = fmaf(qv[i].z, kv[jj].z, s[i][jj]);
                    s[i][jj] = fmaf(qv[i].w, kv[jj].w, s[i][jj]);
                }
        }

#pragma unroll
        for (int i = 0; i < 4; i++) {
            int qg = q0 + ty * 4 + i;
#pragma unroll
            for (int jj = 0; jj < 4; jj++) {
                int jg = jt * BKV + tx + 16 * jj;
                s[i][jj] = (jg > qg) ? -1e30f : s[i][jj] * SCALE_;
            }
        }

#pragma unroll
        for (int i = 0; i < 4; i++) {
            float mx = fmaxf(fmaxf(s[i][0], s[i][1]), fmaxf(s[i][2], s[i][3]));
#pragma unroll
            for (int o = 8; o >= 1; o >>= 1)
                mx = fmaxf(mx, __shfl_xor_sync(0xffffffffu, mx, o));
            float mnew = fmaxf(m_i[i], mx);
            float alpha = __expf(m_i[i] - mnew);
            float rsum = 0.0f;
#pragma unroll
            for (int jj = 0; jj < 4; jj++) {
                float p = __expf(s[i][jj] - mnew);
                rsum += p;
                Ps[(ty * 4 + i) * BKV + tx + 16 * jj] = p;
            }
#pragma unroll
            for (int o = 8; o >= 1; o >>= 1)
                rsum += __shfl_xor_sync(0xffffffffu, rsum, o);
            l_i[i] = l_i[i] * alpha + rsum;
            m_i[i] = mnew;
#pragma unroll
            for (int cc = 0; cc < 5; cc++) acc[i][cc] *= alpha;
        }
        __syncthreads();

        for (int j = 0; j < BKV; j += 4) {
            float4 pv[4];
#pragma unroll
            for (int i = 0; i < 4; i++)
                pv[i] = *(const float4*)&Ps[(ty * 4 + i) * BKV + j];
#pragma unroll
            for (int jj2 = 0; jj2 < 4; jj2++) {
                float vv[5];
#pragma unroll
                for (int cc = 0; cc < 5; cc++)
                    vv[cc] = Vs[(j + jj2) * D_ + tx + 16 * cc];
#pragma unroll
                for (int i = 0; i < 4; i++) {
                    float p = (jj2 == 0) ? pv[i].x : (jj2 == 1) ? pv[i].y
                             : (jj2 == 2) ? pv[i].z : pv[i].w;
#pragma unroll
                    for (int cc = 0; cc < 5; cc++)
                        acc[i][cc] = fmaf(p, vv[cc], acc[i][cc]);
                }
            }
        }
        __syncthreads();
    }

#pragma unroll
    for (int i = 0; i < 4; i++) {
        float inv = 1.0f / l_i[i];
        float* op = outp + (size_t)(b * S_ + q0 + ty * 4 + i) * HID_ + h * D_;
#pragma unroll
        for (int cc = 0; cc < 5; cc++)
            op[tx + 16 * cc] = tf32r(acc[i][cc] * inv);
    }
}

// ---------------------------------------------------------------------------
// kernel_launch
// ---------------------------------------------------------------------------
extern "C" void kernel_launch(void* const* d_in, const int* in_sizes, int n_in,
                              void* d_out, int out_size)
{
    const float* hidden  = (const float*)d_in[0];
    const float* cosp    = (const float*)d_in[1];
    const float* sinp    = (const float*)d_in[2];
    const float* w_qkv   = (const float*)d_in[3];
    const float* b_qkv   = (const float*)d_in[4];
    const float* w_dense = (const float*)d_in[5];
    const float* b_dense = (const float*)d_in[6];
    float* outp = (float*)d_out;

    float *qkv, *attn, *hidT, *wqkvT, *wdT;
    cudaGetSymbolAddress((void**)&qkv,   g_qkv);
    cudaGetSymbolAddress((void**)&attn,  g_attn);
    cudaGetSymbolAddress((void**)&hidT,  g_hidT);
    cudaGetSymbolAddress((void**)&wqkvT, g_wqkvT);
    cudaGetSymbolAddress((void**)&wdT,   g_wdT);

    cudaFuncSetAttribute(mma_gemm,
                         cudaFuncAttributeMaxDynamicSharedMemorySize, GEMM_SMEM);
    cudaFuncSetAttribute(attn_kernel,
                         cudaFuncAttributeMaxDynamicSharedMemorySize, ATTN_SMEM_BYTES);

    // 0) round inputs to tf32 (RNA, unbiased)
    cvt_tf32_kernel<<<(T_ * HID_ / 4 + 255) / 256, 256>>>(
        (const float4*)hidden, (float4*)hidT, T_ * HID_ / 4);
    cvt_tf32_kernel<<<((size_t)QKV_N * HID_ / 4 + 255) / 256, 256>>>(
        (const float4*)w_qkv, (float4*)wqkvT, QKV_N * HID_ / 4);
    cvt_tf32_kernel<<<((size_t)HID_ * HID_ / 4 + 255) / 256, 256>>>(
        (const float4*)w_dense, (float4*)wdT, HID_ * HID_ / 4);

    // 1) QKV GEMM (mma.sync tf32) + bias
    {
        dim3 grid(QKV_N / GN, T_ / GM);   // (30, 32)
        mma_gemm<<<grid, 256, GEMM_SMEM>>>(hidT, wqkvT, b_qkv, qkv, T_, QKV_N, HID_);
    }

    // 2) partial RoPE
    {
        int total = 2 * T_ * H_ * HALF_;
        rope_kernel<<<total / 256, 256>>>(qkv, cosp, sinp);
    }

    // 3) causal flash attention (epilogue rounds to tf32)
    {
        dim3 grid(S_ / BQ, B_ * H_);
        attn_kernel<<<grid, 256, ATTN_SMEM_BYTES>>>(qkv, attn);
    }

    // 4) dense GEMM (mma.sync tf32) + bias -> final output
    {
        dim3 grid(HID_ / GN, T_ / GM);    // (20, 32) -> (10, 32)
        mma_gemm<<<grid, 256, GEMM_SMEM>>>(attn, wdT, b_dense, outp, T_, HID_, HID_);
    }
}

// round 7
// speedup vs baseline: 1.2548x; 1.2548x over previous
#include <cuda_runtime.h>
#include <cuda_bf16.h>
#include <math.h>
#include <stdint.h>

// Problem constants
#define B_   4
#define S_   1024
#define T_   4096
#define H_   32
#define D_   80
#define HID_ 2560
#define QKV_N 7680
#define HALF_ 16
#define SCALE_ 0.11180339887498948f

// ---------------------------------------------------------------------------
// Scratch (device globals)
// ---------------------------------------------------------------------------
__device__ float g_qkv [(size_t)T_ * QKV_N];
__device__ float g_attn[(size_t)T_ * HID_];
__device__ float g_hidT[(size_t)T_ * HID_];
__device__ float g_wqkvT[(size_t)QKV_N * HID_];
__device__ float g_wdT [(size_t)HID_ * HID_];

// ---------------------------------------------------------------------------
// Helpers
// ---------------------------------------------------------------------------
__device__ __forceinline__ float tf32r(float x) {
    uint32_t r;
    asm("cvt.rna.tf32.f32 %0, %1;" : "=r"(r) : "f"(x));
    return __uint_as_float(r);
}

#define CP_ASYNC16(dst, src) \
    asm volatile("cp.async.cg.shared.global [%0], [%1], 16;" :: "r"(dst), "l"(src) : "memory")
#define CP_COMMIT() asm volatile("cp.async.commit_group;" ::: "memory")
#define CP_WAIT0()  asm volatile("cp.async.wait_group 0;" ::: "memory")
#define CP_WAIT1()  asm volatile("cp.async.wait_group 1;" ::: "memory")

#define MMA_TF32(d, a, b) \
    asm volatile("mma.sync.aligned.m16n8k8.row.col.f32.tf32.tf32.f32 " \
        "{%0,%1,%2,%3}, {%4,%5,%6,%7}, {%8,%9}, {%0,%1,%2,%3};" \
        : "+f"((d)[0]), "+f"((d)[1]), "+f"((d)[2]), "+f"((d)[3]) \
        : "r"((a)[0]), "r"((a)[1]), "r"((a)[2]), "r"((a)[3]), \
          "r"((b)[0]), "r"((b)[1]))

__device__ __forceinline__ uint32_t smem_u32(const void* p) {
    uint32_t a;
    asm("{ .reg .u64 t; cvta.to.shared.u64 t, %1; cvt.u32.u64 %0, t; }"
        : "=r"(a) : "l"(p));
    return a;
}

// ---------------------------------------------------------------------------
// tf32 mma.sync GEMM (Round-5 proven config): C = A @ W^T + bias
// CTA 128x128, BK=16, 8 warps (64x32 each), 2 CTAs/SM, double-buffered.
// roundOut!=0 -> emit tf32-RNA-rounded C (for downstream mma consumers).
// ---------------------------------------------------------------------------
#define GM 128
#define GN 128
#define GKC 16
#define PITCH 20
#define STG (128 * PITCH)

__global__ __launch_bounds__(256, 2) void mma_gemm(
    const float* __restrict__ A, const float* __restrict__ W,
    const float* __restrict__ bias, float* __restrict__ C,
    int M, int N, int K, int roundOut)
{
    __shared__ float As[2][STG];
    __shared__ float Bs[2][STG];

    const int tid  = threadIdx.x;
    const int wid  = tid >> 5;
    const int lane = tid & 31;
    const int gid  = lane >> 2;
    const int tig  = lane & 3;
    const int wm   = wid >> 2;
    const int wn   = wid & 3;
    const int m0 = blockIdx.y * GM;
    const int n0 = blockIdx.x * GN;
    const int nk = K / GKC;

    const uint32_t sa = smem_u32(&As[0][0]);
    const uint32_t sbb = smem_u32(&Bs[0][0]);

    const float* srcA[2]; const float* srcB[2]; uint32_t dOff[2];
#pragma unroll
    for (int u = 0; u < 2; u++) {
        int idx = tid + u * 256;
        int row = idx >> 2;
        int kc  = idx & 3;
        srcA[u] = A + (size_t)(m0 + row) * K + kc * 4;
        srcB[u] = W + (size_t)(n0 + row) * K + kc * 4;
        dOff[u] = (uint32_t)(row * PITCH + kc * 4) * 4;
    }

    float acc[4][4][4];
#pragma unroll
    for (int mt = 0; mt < 4; mt++)
#pragma unroll
        for (int nt = 0; nt < 4; nt++)
#pragma unroll
            for (int r = 0; r < 4; r++) acc[mt][nt][r] = 0.0f;

#pragma unroll
    for (int u = 0; u < 2; u++) {
        CP_ASYNC16(sa  + dOff[u], srcA[u]);
        CP_ASYNC16(sbb + dOff[u], srcB[u]);
    }
    CP_COMMIT();

    for (int i = 0; i < nk; i++) {
        const int s = i & 1;
        if (i + 1 < nk) {
            const int s2 = (i + 1) & 1;
            const int kt = (i + 1) * GKC;
            const uint32_t ab = sa  + s2 * (STG * 4);
            const uint32_t bb = sbb + s2 * (STG * 4);
#pragma unroll
            for (int u = 0; u < 2; u++) {
                CP_ASYNC16(ab + dOff[u], srcA[u] + kt);
                CP_ASYNC16(bb + dOff[u], srcB[u] + kt);
            }
            CP_COMMIT();
            CP_WAIT1();
        } else {
            CP_WAIT0();
        }
        __syncthreads();

        const float* as = As[s];
        const float* bs = Bs[s];
#pragma unroll
        for (int ks = 0; ks < 2; ks++) {
            const int k0 = ks * 8;
            uint32_t af[4][4], bf[4][2];
#pragma unroll
            for (int mt = 0; mt < 4; mt++) {
                int r = wm * 64 + mt * 16 + gid;
                af[mt][0] = __float_as_uint(as[r * PITCH + k0 + tig]);
                af[mt][1] = __float_as_uint(as[(r + 8) * PITCH + k0 + tig]);
                af[mt][2] = __float_as_uint(as[r * PITCH + k0 + tig + 4]);
                af[mt][3] = __float_as_uint(as[(r + 8) * PITCH + k0 + tig + 4]);
            }
#pragma unroll
            for (int nt = 0; nt < 4; nt++) {
                int c = wn * 32 + nt * 8 + gid;
                bf[nt][0] = __float_as_uint(bs[c * PITCH + k0 + tig]);
                bf[nt][1] = __float_as_uint(bs[c * PITCH + k0 + tig + 4]);
            }
#pragma unroll
            for (int mt = 0; mt < 4; mt++)
#pragma unroll
                for (int nt = 0; nt < 4; nt++)
                    MMA_TF32(acc[mt][nt], af[mt], bf[nt]);
        }
        __syncthreads();
    }

#pragma unroll
    for (int mt = 0; mt < 4; mt++) {
        int r = m0 + wm * 64 + mt * 16 + gid;
#pragma unroll
        for (int nt = 0; nt < 4; nt++) {
            int c = n0 + wn * 32 + nt * 8 + tig * 2;
            float b0 = bias[c], b1 = bias[c + 1];
            float o0 = acc[mt][nt][0] + b0, o1 = acc[mt][nt][1] + b1;
            float o2 = acc[mt][nt][2] + b0, o3 = acc[mt][nt][3] + b1;
            if (roundOut) {
                o0 = tf32r(o0); o1 = tf32r(o1); o2 = tf32r(o2); o3 = tf32r(o3);
            }
            *(float2*)(C + (size_t)r * N + c)       = make_float2(o0, o1);
            *(float2*)(C + (size_t)(r + 8) * N + c) = make_float2(o2, o3);
        }
    }
}

// ---------------------------------------------------------------------------
// tf32 round (RNA) elementwise convert
// ---------------------------------------------------------------------------
__global__ __launch_bounds__(256) void cvt_tf32_kernel(
    const float4* __restrict__ in, float4* __restrict__ out, int n4)
{
    int i = blockIdx.x * 256 + threadIdx.x;
    if (i >= n4) return;
    float4 v = in[i];
    v.x = tf32r(v.x); v.y = tf32r(v.y); v.z = tf32r(v.z); v.w = tf32r(v.w);
    out[i] = v;
}

// ---------------------------------------------------------------------------
// Partial rotary (in place on q,k of qkv), outputs re-rounded to tf32.
// ---------------------------------------------------------------------------
__global__ __launch_bounds__(256) void rope_kernel(
    float* __restrict__ qkv, const float* __restrict__ cosp,
    const float* __restrict__ sinp)
{
    int idx = blockIdx.x * blockDim.x + threadIdx.x;
    int i = idx & (HALF_ - 1);
    int h = (idx >> 4) & (H_ - 1);
    int t = (idx >> 9) & (T_ - 1);
    int which = idx >> 21;
    float* base = qkv + (size_t)t * QKV_N + which * HID_ + h * D_;
    float c = cosp[t * HALF_ + i];
    float s = sinp[t * HALF_ + i];
    float x1 = base[i];
    float x2 = base[i + HALF_];
    base[i]         = tf32r(x1 * c - x2 * s);
    base[i + HALF_] = tf32r(x2 * c + x1 * s);
}

// ---------------------------------------------------------------------------
// Causal flash attention via mma.sync tf32.
// 128 threads / 4 warps; warp w owns q-rows 16w..16w+15 of a 64-row tile.
// All mma inputs (Q,K,V from rounded qkv; P rounded at store) are exact tf32.
// ---------------------------------------------------------------------------
#define AQ 64
#define AKV 64
#define PQA 84     // Q/K smem pitch (conflict-free frag reads)
#define PVA 88     // V smem pitch   (tig*88 mod 32 = {0,24,16,8})
#define PPS 76     // P smem pitch   (gid*76 mod 32 = gid*12, all distinct)
#define ATTN_SMEM_FLOATS (AQ*PQA + AKV*PQA + AKV*PVA + AQ*PPS)
#define ATTN_SMEM_BYTES  (ATTN_SMEM_FLOATS * 4)

__global__ __launch_bounds__(128) void attn_kernel(
    const float* __restrict__ qkv, float* __restrict__ outp)
{
    extern __shared__ float sm[];
    float* Qs = sm;                      // [AQ][PQA]
    float* Ks = Qs + AQ * PQA;           // [AKV][PQA]
    float* Vs = Ks + AKV * PQA;          // [AKV][PVA]
    float* Ps = Vs + AKV * PVA;          // [AQ][PPS]

    const int bh = blockIdx.y;
    const int b  = bh >> 5;
    const int h  = bh & 31;
    const int qt = blockIdx.x;
    const int q0 = qt * AQ;
    const int tid = threadIdx.x;
    const int lane = tid & 31;
    const int w = tid >> 5;
    const int gid = lane >> 2;
    const int tig = lane & 3;
    const int rq = w * 16;               // warp's q-row base within tile

    const float* Qg = qkv + (size_t)(b * S_) * QKV_N + h * D_;
    const float* Kg = Qg + HID_;
    const float* Vg = Qg + 2 * HID_;

    // Load Q tile (64 x 80)
    for (int u = tid; u < AQ * 20; u += 128) {
        int r = u / 20, c4 = u % 20;
        *(float4*)&Qs[r * PQA + c4 * 4] =
            *(const float4*)(Qg + (size_t)(q0 + r) * QKV_N + c4 * 4);
    }

    float m0v = -1e30f, m1v = -1e30f, l0 = 0.0f, l1 = 0.0f;
    float oacc[10][4];
#pragma unroll
    for (int nt = 0; nt < 10; nt++)
#pragma unroll
        for (int r = 0; r < 4; r++) oacc[nt][r] = 0.0f;

    for (int jt = 0; jt <= qt; jt++) {
        // Load K, V tiles
        for (int u = tid; u < AKV * 20; u += 128) {
            int r = u / 20, c4 = u % 20;
            *(float4*)&Ks[r * PQA + c4 * 4] =
                *(const float4*)(Kg + (size_t)(jt * AKV + r) * QKV_N + c4 * 4);
            *(float4*)&Vs[r * PVA + c4 * 4] =
                *(const float4*)(Vg + (size_t)(jt * AKV + r) * QKV_N + c4 * 4);
        }
        __syncthreads();

        // ---- S = Q K^T (warp rows rq..rq+15, cols 0..63) ----
        float sacc[8][4];
#pragma unroll
        for (int nt = 0; nt < 8; nt++)
#pragma unroll
            for (int r = 0; r < 4; r++) sacc[nt][r] = 0.0f;

#pragma unroll
        for (int kf = 0; kf < 10; kf++) {
            const int k0 = kf * 8;
            uint32_t af[4];
            af[0] = __float_as_uint(Qs[(rq + gid) * PQA + k0 + tig]);
            af[1] = __float_as_uint(Qs[(rq + gid + 8) * PQA + k0 + tig]);
            af[2] = __float_as_uint(Qs[(rq + gid) * PQA + k0 + tig + 4]);
            af[3] = __float_as_uint(Qs[(rq + gid + 8) * PQA + k0 + tig + 4]);
#pragma unroll
            for (int nt = 0; nt < 8; nt++) {
                uint32_t bf[2];
                bf[0] = __float_as_uint(Ks[(nt * 8 + gid) * PQA + k0 + tig]);
                bf[1] = __float_as_uint(Ks[(nt * 8 + gid) * PQA + k0 + tig + 4]);
                MMA_TF32(sacc[nt], af, bf);
            }
        }

        // ---- scale + causal mask ----
        const int r0 = q0 + rq + gid;
        const int r1 = r0 + 8;
#pragma unroll
        for (int nt = 0; nt < 8; nt++) {
            int c0 = jt * AKV + nt * 8 + 2 * tig;
            int c1 = c0 + 1;
            sacc[nt][0] = (c0 > r0) ? -1e30f : sacc[nt][0] * SCALE_;
            sacc[nt][1] = (c1 > r0) ? -1e30f : sacc[nt][1] * SCALE_;
            sacc[nt][2] = (c0 > r1) ? -1e30f : sacc[nt][2] * SCALE_;
            sacc[nt][3] = (c1 > r1) ? -1e30f : sacc[nt][3] * SCALE_;
        }

        // ---- online softmax (rows r0, r1) ----
        float rmax0 = -1e30f, rmax1 = -1e30f;
#pragma unroll
        for (int nt = 0; nt < 8; nt++) {
            rmax0 = fmaxf(rmax0, fmaxf(sacc[nt][0], sacc[nt][1]));
            rmax1 = fmaxf(rmax1, fmaxf(sacc[nt][2], sacc[nt][3]));
        }
#pragma unroll
        for (int o = 1; o <= 2; o <<= 1) {
            rmax0 = fmaxf(rmax0, __shfl_xor_sync(0xffffffffu, rmax0, o));
            rmax1 = fmaxf(rmax1, __shfl_xor_sync(0xffffffffu, rmax1, o));
        }
        float mnew0 = fmaxf(m0v, rmax0), mnew1 = fmaxf(m1v, rmax1);
        float alpha0 = __expf(m0v - mnew0), alpha1 = __expf(m1v - mnew1);

        float rsum0 = 0.0f, rsum1 = 0.0f;
#pragma unroll
        for (int nt = 0; nt < 8; nt++) {
            float p0 = __expf(sacc[nt][0] - mnew0);
            float p1 = __expf(sacc[nt][1] - mnew0);
            float p2 = __expf(sacc[nt][2] - mnew1);
            float p3 = __expf(sacc[nt][3] - mnew1);
            rsum0 += p0 + p1;
            rsum1 += p2 + p3;
            // store rounded P for the PV mma
            *(float2*)&Ps[(rq + gid) * PPS + nt * 8 + 2 * tig] =
                make_float2(tf32r(p0), tf32r(p1));
            *(float2*)&Ps[(rq + gid + 8) * PPS + nt * 8 + 2 * tig] =
                make_float2(tf32r(p2), tf32r(p3));
        }
#pragma unroll
        for (int o = 1; o <= 2; o <<= 1) {
            rsum0 += __shfl_xor_sync(0xffffffffu, rsum0, o);
            rsum1 += __shfl_xor_sync(0xffffffffu, rsum1, o);
        }
        l0 = l0 * alpha0 + rsum0;  m0v = mnew0;
        l1 = l1 * alpha1 + rsum1;  m1v = mnew1;
#pragma unroll
        for (int nt = 0; nt < 10; nt++) {
            oacc[nt][0] *= alpha0; oacc[nt][1] *= alpha0;
            oacc[nt][2] *= alpha1; oacc[nt][3] *= alpha1;
        }
        __syncwarp();   // P store -> P load (same warp, different lanes)

        // ---- O += P V (warp rows rq.., cols 0..79) ----
#pragma unroll
        for (int kf = 0; kf < 8; kf++) {
            const int k0 = kf * 8;
            uint32_t af[4];
            af[0] = __float_as_uint(Ps[(rq + gid) * PPS + k0 + tig]);
            af[1] = __float_as_uint(Ps[(rq + gid + 8) * PPS + k0 + tig]);
            af[2] = __float_as_uint(Ps[(rq + gid) * PPS + k0 + tig + 4]);
            af[3] = __float_as_uint(Ps[(rq + gid + 8) * PPS + k0 + tig + 4]);
#pragma unroll
            for (int nt = 0; nt < 10; nt++) {
                uint32_t bf[2];
                bf[0] = __float_as_uint(Vs[(k0 + tig) * PVA + nt * 8 + gid]);
                bf[1] = __float_as_uint(Vs[(k0 + tig + 4) * PVA + nt * 8 + gid]);
                MMA_TF32(oacc[nt], af, bf);
            }
        }
        __syncthreads();  // all reads of Ks/Vs/Ps done before next tile
    }

    // ---- epilogue: normalize, round to tf32 (dense-GEMM input), store ----
    const float inv0 = 1.0f / l0, inv1 = 1.0f / l1;
    const int gr0 = b * S_ + q0 + rq + gid;
    float* o0p = outp + (size_t)gr0 * HID_ + h * D_;
    float* o1p = o0p + 8 * HID_;
#pragma unroll
    for (int nt = 0; nt < 10; nt++) {
        int c = nt * 8 + 2 * tig;
        *(float2*)(o0p + c) = make_float2(tf32r(oacc[nt][0] * inv0),
                                          tf32r(oacc[nt][1] * inv0));
        *(float2*)(o1p + c) = make_float2(tf32r(oacc[nt][2] * inv1),
                                          tf32r(oacc[nt][3] * inv1));
    }
}

// ---------------------------------------------------------------------------
// kernel_launch
// ---------------------------------------------------------------------------
extern "C" void kernel_launch(void* const* d_in, const int* in_sizes, int n_in,
                              void* d_out, int out_size)
{
    const float* hidden  = (const float*)d_in[0];
    const float* cosp    = (const float*)d_in[1];
    const float* sinp    = (const float*)d_in[2];
    const float* w_qkv   = (const float*)d_in[3];
    const float* b_qkv   = (const float*)d_in[4];
    const float* w_dense = (const float*)d_in[5];
    const float* b_dense = (const float*)d_in[6];
    float* outp = (float*)d_out;

    float *qkv, *attn, *hidT, *wqkvT, *wdT;
    cudaGetSymbolAddress((void**)&qkv,   g_qkv);
    cudaGetSymbolAddress((void**)&attn,  g_attn);
    cudaGetSymbolAddress((void**)&hidT,  g_hidT);
    cudaGetSymbolAddress((void**)&wqkvT, g_wqkvT);
    cudaGetSymbolAddress((void**)&wdT,   g_wdT);

    cudaFuncSetAttribute(attn_kernel,
                         cudaFuncAttributeMaxDynamicSharedMemorySize, ATTN_SMEM_BYTES);

    // 0) round inputs to tf32 (RNA, unbiased)
    cvt_tf32_kernel<<<(T_ * HID_ / 4 + 255) / 256, 256>>>(
        (const float4*)hidden, (float4*)hidT, T_ * HID_ / 4);
    cvt_tf32_kernel<<<((size_t)QKV_N * HID_ / 4 + 255) / 256, 256>>>(
        (const float4*)w_qkv, (float4*)wqkvT, QKV_N * HID_ / 4);
    cvt_tf32_kernel<<<((size_t)HID_ * HID_ / 4 + 255) / 256, 256>>>(
        (const float4*)w_dense, (float4*)wdT, HID_ * HID_ / 4);

    // 1) QKV GEMM (mma.sync tf32) + bias, tf32-rounded output
    {
        dim3 grid(QKV_N / GN, T_ / GM);   // (60, 32)
        mma_gemm<<<grid, 256>>>(hidT, wqkvT, b_qkv, qkv, T_, QKV_N, HID_, 1);
    }

    // 2) partial RoPE (re-rounds rotated dims)
    {
        int total = 2 * T_ * H_ * HALF_;
        rope_kernel<<<total / 256, 256>>>(qkv, cosp, sinp);
    }

    // 3) causal flash attention (mma.sync tf32)
    {
        dim3 grid(S_ / AQ, B_ * H_);      // (16, 128)
        attn_kernel<<<grid, 128, ATTN_SMEM_BYTES>>>(qkv, attn);
    }

    // 4) dense GEMM (mma.sync tf32) + bias -> final output (no rounding)
    {
        dim3 grid(HID_ / GN, T_ / GM);    // (20, 32)
        mma_gemm<<<grid, 256>>>(attn, wdT, b_dense, outp, T_, HID_, HID_, 0);
    }
}

// round 8
// speedup vs baseline: 1.5029x; 1.1977x over previous
#include <cuda_runtime.h>
#include <cuda_bf16.h>
#include <math.h>
#include <stdint.h>

// Problem constants
#define B_   4
#define S_   1024
#define T_   4096
#define H_   32
#define D_   80
#define HID_ 2560
#define QKV_N 7680
#define HALF_ 16
#define SCALE_ 0.11180339887498948f

// ---------------------------------------------------------------------------
// Scratch (device globals)
// ---------------------------------------------------------------------------
__device__ float g_qkv [(size_t)T_ * QKV_N];
__device__ float g_attn[(size_t)T_ * HID_];
__device__ float g_hidT[(size_t)T_ * HID_];
__device__ float g_wqkvT[(size_t)QKV_N * HID_];
__device__ float g_wdT [(size_t)HID_ * HID_];

// ---------------------------------------------------------------------------
// Helpers
// ---------------------------------------------------------------------------
__device__ __forceinline__ float tf32r(float x) {
    uint32_t r;
    asm("cvt.rna.tf32.f32 %0, %1;" : "=r"(r) : "f"(x));
    return __uint_as_float(r);
}

#define CP_ASYNC16(dst, src) \
    asm volatile("cp.async.cg.shared.global [%0], [%1], 16;" :: "r"(dst), "l"(src) : "memory")
#define CP_COMMIT() asm volatile("cp.async.commit_group;" ::: "memory")
#define CP_WAIT0()  asm volatile("cp.async.wait_group 0;" ::: "memory")
#define CP_WAIT1()  asm volatile("cp.async.wait_group 1;" ::: "memory")

#define MMA_TF32(d, a, b) \
    asm volatile("mma.sync.aligned.m16n8k8.row.col.f32.tf32.tf32.f32 " \
        "{%0,%1,%2,%3}, {%4,%5,%6,%7}, {%8,%9}, {%0,%1,%2,%3};" \
        : "+f"((d)[0]), "+f"((d)[1]), "+f"((d)[2]), "+f"((d)[3]) \
        : "r"((a)[0]), "r"((a)[1]), "r"((a)[2]), "r"((a)[3]), \
          "r"((b)[0]), "r"((b)[1]))

__device__ __forceinline__ uint32_t smem_u32(const void* p) {
    uint32_t a;
    asm("{ .reg .u64 t; cvta.to.shared.u64 t, %1; cvt.u32.u64 %0, t; }"
        : "=r"(a) : "l"(p));
    return a;
}

// ---------------------------------------------------------------------------
// tf32 mma.sync GEMM: C = A @ W^T + bias
// CTA 128x128, BK=32, 8 warps (64x32 each), 2 CTAs/SM, double-buffered.
// PITCH=36 floats (144B rows, 16B aligned, conflict-free frag reads).
// roundOut!=0 -> emit tf32-RNA-rounded C.
// ---------------------------------------------------------------------------
#define GM 128
#define GN 128
#define GKC 32
#define PITCH 36
#define STG (128 * PITCH)                 // 4608 floats per stage
#define GEMM_SMEM (4 * STG * 4)           // 73728 bytes (A[2] + B[2])

__global__ __launch_bounds__(256, 2) void mma_gemm(
    const float* __restrict__ A, const float* __restrict__ W,
    const float* __restrict__ bias, float* __restrict__ C,
    int M, int N, int K, int roundOut)
{
    extern __shared__ float smf[];
    float* Asm = smf;                     // [2][STG]
    float* Bsm = smf + 2 * STG;           // [2][STG]

    const int tid  = threadIdx.x;
    const int wid  = tid >> 5;
    const int lane = tid & 31;
    const int gid  = lane >> 2;
    const int tig  = lane & 3;
    const int wm   = wid >> 2;
    const int wn   = wid & 3;
    const int m0 = blockIdx.y * GM;
    const int n0 = blockIdx.x * GN;
    const int nk = K / GKC;

    const uint32_t sa = smem_u32(Asm);
    const uint32_t sb = smem_u32(Bsm);

    // cp.async mapping: 128 rows x 8 float4-chunks per operand -> 4 per thread,
    // u-th chunk at source +u*32*K, dest +u*4608 bytes.
    const int rowL = tid >> 3;            // 0..31
    const int kcL  = tid & 7;             // 0..7
    const float* srcA0 = A + (size_t)(m0 + rowL) * K + kcL * 4;
    const float* srcB0 = W + (size_t)(n0 + rowL) * K + kcL * 4;
    const uint32_t d0 = (uint32_t)(rowL * 144 + kcL * 16);
    const size_t rstep = (size_t)32 * K;

    float acc[4][4][4];
#pragma unroll
    for (int mt = 0; mt < 4; mt++)
#pragma unroll
        for (int nt = 0; nt < 4; nt++)
#pragma unroll
            for (int r = 0; r < 4; r++) acc[mt][nt][r] = 0.0f;

    // Prologue: stage 0
#pragma unroll
    for (int u = 0; u < 4; u++) {
        CP_ASYNC16(sa + d0 + u * 4608, srcA0 + u * rstep);
        CP_ASYNC16(sb + d0 + u * 4608, srcB0 + u * rstep);
    }
    CP_COMMIT();

    for (int i = 0; i < nk; i++) {
        const int s = i & 1;
        if (i + 1 < nk) {
            const int s2 = (i + 1) & 1;
            const int kt = (i + 1) * GKC;
            const uint32_t ab = sa + s2 * (STG * 4);
            const uint32_t bb = sb + s2 * (STG * 4);
#pragma unroll
            for (int u = 0; u < 4; u++) {
                CP_ASYNC16(ab + d0 + u * 4608, srcA0 + kt + u * rstep);
                CP_ASYNC16(bb + d0 + u * 4608, srcB0 + kt + u * rstep);
            }
            CP_COMMIT();
            CP_WAIT1();
        } else {
            CP_WAIT0();
        }
        __syncthreads();

        const float* as = Asm + s * STG;
        const float* bs = Bsm + s * STG;
#pragma unroll
        for (int ks = 0; ks < 4; ks++) {
            const int k0 = ks * 8;
            uint32_t af[4][4], bf[4][2];
#pragma unroll
            for (int mt = 0; mt < 4; mt++) {
                int r = wm * 64 + mt * 16 + gid;
                af[mt][0] = __float_as_uint(as[r * PITCH + k0 + tig]);
                af[mt][1] = __float_as_uint(as[(r + 8) * PITCH + k0 + tig]);
                af[mt][2] = __float_as_uint(as[r * PITCH + k0 + tig + 4]);
                af[mt][3] = __float_as_uint(as[(r + 8) * PITCH + k0 + tig + 4]);
            }
#pragma unroll
            for (int nt = 0; nt < 4; nt++) {
                int c = wn * 32 + nt * 8 + gid;
                bf[nt][0] = __float_as_uint(bs[c * PITCH + k0 + tig]);
                bf[nt][1] = __float_as_uint(bs[c * PITCH + k0 + tig + 4]);
            }
#pragma unroll
            for (int mt = 0; mt < 4; mt++)
#pragma unroll
                for (int nt = 0; nt < 4; nt++)
                    MMA_TF32(acc[mt][nt], af[mt], bf[nt]);
        }
        __syncthreads();
    }

#pragma unroll
    for (int mt = 0; mt < 4; mt++) {
        int r = m0 + wm * 64 + mt * 16 + gid;
#pragma unroll
        for (int nt = 0; nt < 4; nt++) {
            int c = n0 + wn * 32 + nt * 8 + tig * 2;
            float b0 = bias[c], b1 = bias[c + 1];
            float o0 = acc[mt][nt][0] + b0, o1 = acc[mt][nt][1] + b1;
            float o2 = acc[mt][nt][2] + b0, o3 = acc[mt][nt][3] + b1;
            if (roundOut) {
                o0 = tf32r(o0); o1 = tf32r(o1); o2 = tf32r(o2); o3 = tf32r(o3);
            }
            *(float2*)(C + (size_t)r * N + c)       = make_float2(o0, o1);
            *(float2*)(C + (size_t)(r + 8) * N + c) = make_float2(o2, o3);
        }
    }
}

// ---------------------------------------------------------------------------
// tf32 round (RNA) elementwise convert
// ---------------------------------------------------------------------------
__global__ __launch_bounds__(256) void cvt_tf32_kernel(
    const float4* __restrict__ in, float4* __restrict__ out, int n4)
{
    int i = blockIdx.x * 256 + threadIdx.x;
    if (i >= n4) return;
    float4 v = in[i];
    v.x = tf32r(v.x); v.y = tf32r(v.y); v.z = tf32r(v.z); v.w = tf32r(v.w);
    out[i] = v;
}

// ---------------------------------------------------------------------------
// Partial rotary (in place on q,k of qkv), outputs re-rounded to tf32.
// ---------------------------------------------------------------------------
__global__ __launch_bounds__(256) void rope_kernel(
    float* __restrict__ qkv, const float* __restrict__ cosp,
    const float* __restrict__ sinp)
{
    int idx = blockIdx.x * blockDim.x + threadIdx.x;
    int i = idx & (HALF_ - 1);
    int h = (idx >> 4) & (H_ - 1);
    int t = (idx >> 9) & (T_ - 1);
    int which = idx >> 21;
    float* base = qkv + (size_t)t * QKV_N + which * HID_ + h * D_;
    float c = cosp[t * HALF_ + i];
    float s = sinp[t * HALF_ + i];
    float x1 = base[i];
    float x2 = base[i + HALF_];
    base[i]         = tf32r(x1 * c - x2 * s);
    base[i + HALF_] = tf32r(x2 * c + x1 * s);
}

// ---------------------------------------------------------------------------
// Causal flash attention via mma.sync tf32 (Round-7 proven).
// ---------------------------------------------------------------------------
#define AQ 64
#define AKV 64
#define PQA 84
#define PVA 88
#define PPS 76
#define ATTN_SMEM_FLOATS (AQ*PQA + AKV*PQA + AKV*PVA + AQ*PPS)
#define ATTN_SMEM_BYTES  (ATTN_SMEM_FLOATS * 4)

__global__ __launch_bounds__(128) void attn_kernel(
    const float* __restrict__ qkv, float* __restrict__ outp)
{
    extern __shared__ float sm[];
    float* Qs = sm;
    float* Ks = Qs + AQ * PQA;
    float* Vs = Ks + AKV * PQA;
    float* Ps = Vs + AKV * PVA;

    const int bh = blockIdx.y;
    const int b  = bh >> 5;
    const int h  = bh & 31;
    const int qt = blockIdx.x;
    const int q0 = qt * AQ;
    const int tid = threadIdx.x;
    const int lane = tid & 31;
    const int w = tid >> 5;
    const int gid = lane >> 2;
    const int tig = lane & 3;
    const int rq = w * 16;

    const float* Qg = qkv + (size_t)(b * S_) * QKV_N + h * D_;
    const float* Kg = Qg + HID_;
    const float* Vg = Qg + 2 * HID_;

    for (int u = tid; u < AQ * 20; u += 128) {
        int r = u / 20, c4 = u % 20;
        *(float4*)&Qs[r * PQA + c4 * 4] =
            *(const float4*)(Qg + (size_t)(q0 + r) * QKV_N + c4 * 4);
    }

    float m0v = -1e30f, m1v = -1e30f, l0 = 0.0f, l1 = 0.0f;
    float oacc[10][4];
#pragma unroll
    for (int nt = 0; nt < 10; nt++)
#pragma unroll
        for (int r = 0; r < 4; r++) oacc[nt][r] = 0.0f;

    for (int jt = 0; jt <= qt; jt++) {
        for (int u = tid; u < AKV * 20; u += 128) {
            int r = u / 20, c4 = u % 20;
            *(float4*)&Ks[r * PQA + c4 * 4] =
                *(const float4*)(Kg + (size_t)(jt * AKV + r) * QKV_N + c4 * 4);
            *(float4*)&Vs[r * PVA + c4 * 4] =
                *(const float4*)(Vg + (size_t)(jt * AKV + r) * QKV_N + c4 * 4);
        }
        __syncthreads();

        float sacc[8][4];
#pragma unroll
        for (int nt = 0; nt < 8; nt++)
#pragma unroll
            for (int r = 0; r < 4; r++) sacc[nt][r] = 0.0f;

#pragma unroll
        for (int kf = 0; kf < 10; kf++) {
            const int k0 = kf * 8;
            uint32_t af[4];
            af[0] = __float_as_uint(Qs[(rq + gid) * PQA + k0 + tig]);
            af[1] = __float_as_uint(Qs[(rq + gid + 8) * PQA + k0 + tig]);
            af[2] = __float_as_uint(Qs[(rq + gid) * PQA + k0 + tig + 4]);
            af[3] = __float_as_uint(Qs[(rq + gid + 8) * PQA + k0 + tig + 4]);
#pragma unroll
            for (int nt = 0; nt < 8; nt++) {
                uint32_t bf[2];
                bf[0] = __float_as_uint(Ks[(nt * 8 + gid) * PQA + k0 + tig]);
                bf[1] = __float_as_uint(Ks[(nt * 8 + gid) * PQA + k0 + tig + 4]);
                MMA_TF32(sacc[nt], af, bf);
            }
        }

        const int r0 = q0 + rq + gid;
        const int r1 = r0 + 8;
#pragma unroll
        for (int nt = 0; nt < 8; nt++) {
            int c0 = jt * AKV + nt * 8 + 2 * tig;
            int c1 = c0 + 1;
            sacc[nt][0] = (c0 > r0) ? -1e30f : sacc[nt][0] * SCALE_;
            sacc[nt][1] = (c1 > r0) ? -1e30f : sacc[nt][1] * SCALE_;
            sacc[nt][2] = (c0 > r1) ? -1e30f : sacc[nt][2] * SCALE_;
            sacc[nt][3] = (c1 > r1) ? -1e30f : sacc[nt][3] * SCALE_;
        }

        float rmax0 = -1e30f, rmax1 = -1e30f;
#pragma unroll
        for (int nt = 0; nt < 8; nt++) {
            rmax0 = fmaxf(rmax0, fmaxf(sacc[nt][0], sacc[nt][1]));
            rmax1 = fmaxf(rmax1, fmaxf(sacc[nt][2], sacc[nt][3]));
        }
#pragma unroll
        for (int o = 1; o <= 2; o <<= 1) {
            rmax0 = fmaxf(rmax0, __shfl_xor_sync(0xffffffffu, rmax0, o));
            rmax1 = fmaxf(rmax1, __shfl_xor_sync(0xffffffffu, rmax1, o));
        }
        float mnew0 = fmaxf(m0v, rmax0), mnew1 = fmaxf(m1v, rmax1);
        float alpha0 = __expf(m0v - mnew0), alpha1 = __expf(m1v - mnew1);

        float rsum0 = 0.0f, rsum1 = 0.0f;
#pragma unroll
        for (int nt = 0; nt < 8; nt++) {
            float p0 = __expf(sacc[nt][0] - mnew0);
            float p1 = __expf(sacc[nt][1] - mnew0);
            float p2 = __expf(sacc[nt][2] - mnew1);
            float p3 = __expf(sacc[nt][3] - mnew1);
            rsum0 += p0 + p1;
            rsum1 += p2 + p3;
            *(float2*)&Ps[(rq + gid) * PPS + nt * 8 + 2 * tig] =
                make_float2(tf32r(p0), tf32r(p1));
            *(float2*)&Ps[(rq + gid + 8) * PPS + nt * 8 + 2 * tig] =
                make_float2(tf32r(p2), tf32r(p3));
        }
#pragma unroll
        for (int o = 1; o <= 2; o <<= 1) {
            rsum0 += __shfl_xor_sync(0xffffffffu, rsum0, o);
            rsum1 += __shfl_xor_sync(0xffffffffu, rsum1, o);
        }
        l0 = l0 * alpha0 + rsum0;  m0v = mnew0;
        l1 = l1 * alpha1 + rsum1;  m1v = mnew1;
#pragma unroll
        for (int nt = 0; nt < 10; nt++) {
            oacc[nt][0] *= alpha0; oacc[nt][1] *= alpha0;
            oacc[nt][2] *= alpha1; oacc[nt][3] *= alpha1;
        }
        __syncwarp();

#pragma unroll
        for (int kf = 0; kf < 8; kf++) {
            const int k0 = kf * 8;
            uint32_t af[4];
            af[0] = __float_as_uint(Ps[(rq + gid) * PPS + k0 + tig]);
            af[1] = __float_as_uint(Ps[(rq + gid + 8) * PPS + k0 + tig]);
            af[2] = __float_as_uint(Ps[(rq + gid) * PPS + k0 + tig + 4]);
            af[3] = __float_as_uint(Ps[(rq + gid + 8) * PPS + k0 + tig + 4]);
#pragma unroll
            for (int nt = 0; nt < 10; nt++) {
                uint32_t bf[2];
                bf[0] = __float_as_uint(Vs[(k0 + tig) * PVA + nt * 8 + gid]);
                bf[1] = __float_as_uint(Vs[(k0 + tig + 4) * PVA + nt * 8 + gid]);
                MMA_TF32(oacc[nt], af, bf);
            }
        }
        __syncthreads();
    }

    const float inv0 = 1.0f / l0, inv1 = 1.0f / l1;
    const int gr0 = b * S_ + q0 + rq + gid;
    float* o0p = outp + (size_t)gr0 * HID_ + h * D_;
    float* o1p = o0p + 8 * HID_;
#pragma unroll
    for (int nt = 0; nt < 10; nt++) {
        int c = nt * 8 + 2 * tig;
        *(float2*)(o0p + c) = make_float2(tf32r(oacc[nt][0] * inv0),
                                          tf32r(oacc[nt][1] * inv0));
        *(float2*)(o1p + c) = make_float2(tf32r(oacc[nt][2] * inv1),
                                          tf32r(oacc[nt][3] * inv1));
    }
}

// ---------------------------------------------------------------------------
// kernel_launch
// ---------------------------------------------------------------------------
extern "C" void kernel_launch(void* const* d_in, const int* in_sizes, int n_in,
                              void* d_out, int out_size)
{
    const float* hidden  = (const float*)d_in[0];
    const float* cosp    = (const float*)d_in[1];
    const float* sinp    = (const float*)d_in[2];
    const float* w_qkv   = (const float*)d_in[3];
    const float* b_qkv   = (const float*)d_in[4];
    const float* w_dense = (const float*)d_in[5];
    const float* b_dense = (const float*)d_in[6];
    float* outp = (float*)d_out;

    float *qkv, *attn, *hidT, *wqkvT, *wdT;
    cudaGetSymbolAddress((void**)&qkv,   g_qkv);
    cudaGetSymbolAddress((void**)&attn,  g_attn);
    cudaGetSymbolAddress((void**)&hidT,  g_hidT);
    cudaGetSymbolAddress((void**)&wqkvT, g_wqkvT);
    cudaGetSymbolAddress((void**)&wdT,   g_wdT);

    cudaFuncSetAttribute(mma_gemm,
                         cudaFuncAttributeMaxDynamicSharedMemorySize, GEMM_SMEM);
    cudaFuncSetAttribute(attn_kernel,
                         cudaFuncAttributeMaxDynamicSharedMemorySize, ATTN_SMEM_BYTES);

    // 0) round inputs to tf32 (RNA, unbiased)
    cvt_tf32_kernel<<<(T_ * HID_ / 4 + 255) / 256, 256>>>(
        (const float4*)hidden, (float4*)hidT, T_ * HID_ / 4);
    cvt_tf32_kernel<<<((size_t)QKV_N * HID_ / 4 + 255) / 256, 256>>>(
        (const float4*)w_qkv, (float4*)wqkvT, QKV_N * HID_ / 4);
    cvt_tf32_kernel<<<((size_t)HID_ * HID_ / 4 + 255) / 256, 256>>>(
        (const float4*)w_dense, (float4*)wdT, HID_ * HID_ / 4);

    // 1) QKV GEMM (mma.sync tf32) + bias, tf32-rounded output
    {
        dim3 grid(QKV_N / GN, T_ / GM);   // (60, 32)
        mma_gemm<<<grid, 256, GEMM_SMEM>>>(hidT, wqkvT, b_qkv, qkv,
                                           T_, QKV_N, HID_, 1);
    }

    // 2) partial RoPE (re-rounds rotated dims)
    {
        int total = 2 * T_ * H_ * HALF_;
        rope_kernel<<<total / 256, 256>>>(qkv, cosp, sinp);
    }

    // 3) causal flash attention (mma.sync tf32)
    {
        dim3 grid(S_ / AQ, B_ * H_);      // (16, 128)
        attn_kernel<<<grid, 128, ATTN_SMEM_BYTES>>>(qkv, attn);
    }

    // 4) dense GEMM (mma.sync tf32) + bias -> final output (no rounding)
    {
        dim3 grid(HID_ / GN, T_ / GM);    // (20, 32)
        mma_gemm<<<grid, 256, GEMM_SMEM>>>(attn, wdT, b_dense, outp,
                                           T_, HID_, HID_, 0);
    }
}